// round 10
// baseline (speedup 1.0000x reference)
#include <cuda_runtime.h>

// Problem constants
#define B    4
#define L    1024
#define H    16
#define U    64
#define DIN  1024
#define DM   1024        // H*U
#define BL   (B*L)       // 4096
#define OUT_ELEMS  (B*L*U)          // 262144
#define ATTN_ELEMS ((long long)B*H*L*L)  // 67108864

// Scratch (device globals — no cudaMalloc allowed). Total: 68MB.
// IMPORTANT: these symbols are ONLY referenced from DEVICE code. Passing a
// __device__ symbol as a host-side kernel argument is silent UB (host shadow
// address) — that was the root cause of rounds 1-9 failing.
__device__ float g_q[B*H*L*U];          // head-split Q: (B,H,L,U)
__device__ float g_k[B*H*L*U];
__device__ float g_v[B*H*L*U];
__device__ float g_ctx[BL*DM];          // concat layout (B,L,H*U)
__device__ float g_attn1[L*L];          // per-head scratch for fallback path

// ---------------------------------------------------------------------------
// Kernel 1: projection GEMM. C[m,n] = sum_k A[m,k]*W[k,n] + bias[n]
// A: (BL, DIN) row-major.  W: (DIN, DM) row-major.
// Output selected by `which` (0:g_q, 1:g_k, 2:g_v), written head-split:
// outHS[((b*H+h)*L+l)*U+u], n = h*U+u.
// Tile 128x128, BK=16, 256 threads, 8x8 per-thread.
// ---------------------------------------------------------------------------
__global__ __launch_bounds__(256) void proj_kernel(
    const float* __restrict__ A, const float* __restrict__ W,
    const float* __restrict__ bias, int which)
{
    float* outHS = (which == 0) ? g_q : (which == 1) ? g_k : g_v;

    __shared__ float As[16][128];   // transposed: As[k][m]
    __shared__ float Ws[16][128];   // Ws[k][n]

    const int bm = blockIdx.y * 128;
    const int bn = blockIdx.x * 128;
    const int tid = threadIdx.x;
    const int ty = tid >> 4;
    const int tx = tid & 15;

    float acc[8][8];
    #pragma unroll
    for (int i = 0; i < 8; i++)
        #pragma unroll
        for (int j = 0; j < 8; j++) acc[i][j] = 0.f;

    for (int k0 = 0; k0 < DIN; k0 += 16) {
        #pragma unroll
        for (int it = 0; it < 2; it++) {
            int id = tid + it * 256;          // 0..511
            int r  = id >> 2;                 // 0..127
            int c4 = (id & 3) * 4;            // 0,4,8,12
            float4 v = *(const float4*)&A[(size_t)(bm + r) * DIN + k0 + c4];
            As[c4+0][r] = v.x; As[c4+1][r] = v.y;
            As[c4+2][r] = v.z; As[c4+3][r] = v.w;
        }
        #pragma unroll
        for (int it = 0; it < 2; it++) {
            int id = tid + it * 256;
            int r  = id >> 5;                 // 0..15
            int c  = (id & 31) * 4;           // 0..124
            *(float4*)&Ws[r][c] = *(const float4*)&W[(size_t)(k0 + r) * DM + bn + c];
        }
        __syncthreads();

        #pragma unroll
        for (int k = 0; k < 16; k++) {
            float a[8], bb[8];
            #pragma unroll
            for (int i = 0; i < 8; i++) a[i] = As[k][ty*8 + i];
            #pragma unroll
            for (int j = 0; j < 8; j++) bb[j] = Ws[k][tx*8 + j];
            #pragma unroll
            for (int i = 0; i < 8; i++)
                #pragma unroll
                for (int j = 0; j < 8; j++)
                    acc[i][j] = fmaf(a[i], bb[j], acc[i][j]);
        }
        __syncthreads();
    }

    #pragma unroll
    for (int i = 0; i < 8; i++) {
        int m = bm + ty*8 + i;
        int b_ = m / L, l = m % L;
        #pragma unroll
        for (int j = 0; j < 8; j++) {
            int n = bn + tx*8 + j;
            int h = n / U, u = n % U;
            outHS[(((size_t)b_*H + h)*L + l)*U + u] = acc[i][j] + bias[n];
        }
    }
}

// ---------------------------------------------------------------------------
// Kernel 2: logits. For head z = z0 + blockIdx.z: S = Q(LxU) * K^T(UxL) * scale
// If attnp is null, uses g_attn1 (device-side symbol access — legal).
// ---------------------------------------------------------------------------
__global__ __launch_bounds__(256) void logits_kernel(
    float* attnp, int z0, size_t zstride)
{
    float* attn = attnp ? attnp : g_attn1;

    __shared__ float Qs[16][128];
    __shared__ float Ks[16][128];

    const int z  = z0 + blockIdx.z;
    const int m0 = blockIdx.y * 128;
    const int n0 = blockIdx.x * 128;
    const int tid = threadIdx.x;
    const int ty = tid >> 4, tx = tid & 15;

    const float* Q = g_q + (size_t)z * L * U;
    const float* K = g_k + (size_t)z * L * U;

    float acc[8][8];
    #pragma unroll
    for (int i = 0; i < 8; i++)
        #pragma unroll
        for (int j = 0; j < 8; j++) acc[i][j] = 0.f;

    for (int k0 = 0; k0 < U; k0 += 16) {
        #pragma unroll
        for (int it = 0; it < 2; it++) {
            int id = tid + it * 256;
            int r  = id >> 2;
            int c4 = (id & 3) * 4;
            float4 v = *(const float4*)&Q[(size_t)(m0 + r) * U + k0 + c4];
            Qs[c4+0][r] = v.x; Qs[c4+1][r] = v.y;
            Qs[c4+2][r] = v.z; Qs[c4+3][r] = v.w;
            float4 w = *(const float4*)&K[(size_t)(n0 + r) * U + k0 + c4];
            Ks[c4+0][r] = w.x; Ks[c4+1][r] = w.y;
            Ks[c4+2][r] = w.z; Ks[c4+3][r] = w.w;
        }
        __syncthreads();

        #pragma unroll
        for (int k = 0; k < 16; k++) {
            float a[8], bb[8];
            #pragma unroll
            for (int i = 0; i < 8; i++) a[i] = Qs[k][ty*8 + i];
            #pragma unroll
            for (int j = 0; j < 8; j++) bb[j] = Ks[k][tx*8 + j];
            #pragma unroll
            for (int i = 0; i < 8; i++)
                #pragma unroll
                for (int j = 0; j < 8; j++)
                    acc[i][j] = fmaf(a[i], bb[j], acc[i][j]);
        }
        __syncthreads();
    }

    const float scale = 0.125f;   // 1/sqrt(64)
    #pragma unroll
    for (int i = 0; i < 8; i++) {
        size_t rowbase = (size_t)blockIdx.z * zstride
                       + (size_t)(m0 + ty*8 + i) * L + n0;
        #pragma unroll
        for (int j = 0; j < 8; j++)
            attn[rowbase + tx*8 + j] = acc[i][j] * scale;
    }
}

// ---------------------------------------------------------------------------
// Kernel 3: row softmax in-place. One block (256 thr) per row of 1024.
// ---------------------------------------------------------------------------
__global__ __launch_bounds__(256) void softmax_kernel(float* attnp)
{
    float* attn = attnp ? attnp : g_attn1;
    const int tid = threadIdx.x;
    float4* p = (float4*)(attn + (size_t)blockIdx.x * L);
    float4 v = p[tid];

    float m = fmaxf(fmaxf(v.x, v.y), fmaxf(v.z, v.w));
    #pragma unroll
    for (int o = 16; o > 0; o >>= 1) m = fmaxf(m, __shfl_xor_sync(0xffffffffu, m, o));
    __shared__ float sm[8];
    __shared__ float ss[8];
    int wid = tid >> 5, lane = tid & 31;
    if (lane == 0) sm[wid] = m;
    __syncthreads();
    m = sm[0];
    #pragma unroll
    for (int i = 1; i < 8; i++) m = fmaxf(m, sm[i]);

    v.x = __expf(v.x - m); v.y = __expf(v.y - m);
    v.z = __expf(v.z - m); v.w = __expf(v.w - m);
    float s = v.x + v.y + v.z + v.w;
    #pragma unroll
    for (int o = 16; o > 0; o >>= 1) s += __shfl_xor_sync(0xffffffffu, s, o);
    if (lane == 0) ss[wid] = s;
    __syncthreads();
    s = 0.f;
    #pragma unroll
    for (int i = 0; i < 8; i++) s += ss[i];

    float inv = 1.0f / s;
    v.x *= inv; v.y *= inv; v.z *= inv; v.w *= inv;
    p[tid] = v;
}

// ---------------------------------------------------------------------------
// Kernel 4: ctx. For head z = z0 + blockIdx.z: ctx(LxU) = attn(LxL) @ V(LxU)
// ---------------------------------------------------------------------------
__global__ __launch_bounds__(256) void ctx_kernel(
    const float* attnp, int z0, size_t zstride)
{
    const float* attn = attnp ? attnp : g_attn1;

    __shared__ float As[32][128];
    __shared__ float Vs[32][64];

    const int z  = z0 + blockIdx.z;
    const int m0 = blockIdx.x * 128;
    const int tid = threadIdx.x;
    const int ty = tid >> 4, tx = tid & 15;

    const float* Vh = g_v + (size_t)z * L * U;
    const float* attnZ = attn + (size_t)blockIdx.z * zstride;

    float acc[8][4];
    #pragma unroll
    for (int i = 0; i < 8; i++)
        #pragma unroll
        for (int j = 0; j < 4; j++) acc[i][j] = 0.f;

    for (int kk = 0; kk < L; kk += 32) {
        #pragma unroll
        for (int it = 0; it < 4; it++) {
            int id = tid + it * 256;
            int r  = id >> 3;
            int c4 = (id & 7) * 4;
            float4 v = *(const float4*)&attnZ[(size_t)(m0 + r) * L + kk + c4];
            As[c4+0][r] = v.x; As[c4+1][r] = v.y;
            As[c4+2][r] = v.z; As[c4+3][r] = v.w;
        }
        #pragma unroll
        for (int it = 0; it < 2; it++) {
            int id = tid + it * 256;
            int r  = id >> 4;
            int c4 = (id & 15) * 4;
            *(float4*)&Vs[r][c4] = *(const float4*)&Vh[(size_t)(kk + r) * U + c4];
        }
        __syncthreads();

        #pragma unroll
        for (int k = 0; k < 32; k++) {
            float a[8], bb[4];
            #pragma unroll
            for (int i = 0; i < 8; i++) a[i] = As[k][ty*8 + i];
            #pragma unroll
            for (int j = 0; j < 4; j++) bb[j] = Vs[k][tx*4 + j];
            #pragma unroll
            for (int i = 0; i < 8; i++)
                #pragma unroll
                for (int j = 0; j < 4; j++)
                    acc[i][j] = fmaf(a[i], bb[j], acc[i][j]);
        }
        __syncthreads();
    }

    const int b_ = z / H, h = z % H;
    #pragma unroll
    for (int i = 0; i < 8; i++) {
        int m = m0 + ty*8 + i;
        size_t rowbase = ((size_t)b_*L + m) * DM + h*U;
        #pragma unroll
        for (int j = 0; j < 4; j++)
            g_ctx[rowbase + tx*4 + j] = acc[i][j];
    }
}

// ---------------------------------------------------------------------------
// Kernel 5: output projection. out(BLxU) = g_ctx(BLxDM) @ wo(DMxU) + bo
// ---------------------------------------------------------------------------
__global__ __launch_bounds__(256) void outproj_kernel(
    const float* __restrict__ wo, const float* __restrict__ bo,
    float* __restrict__ out)
{
    __shared__ float As[32][128];
    __shared__ float Ws[32][64];

    const int m0 = blockIdx.x * 128;
    const int tid = threadIdx.x;
    const int ty = tid >> 4, tx = tid & 15;

    float acc[8][4];
    #pragma unroll
    for (int i = 0; i < 8; i++)
        #pragma unroll
        for (int j = 0; j < 4; j++) acc[i][j] = 0.f;

    for (int k0 = 0; k0 < DM; k0 += 32) {
        #pragma unroll
        for (int it = 0; it < 4; it++) {
            int id = tid + it * 256;
            int r  = id >> 3;
            int c4 = (id & 7) * 4;
            float4 v = *(const float4*)&g_ctx[(size_t)(m0 + r) * DM + k0 + c4];
            As[c4+0][r] = v.x; As[c4+1][r] = v.y;
            As[c4+2][r] = v.z; As[c4+3][r] = v.w;
        }
        #pragma unroll
        for (int it = 0; it < 2; it++) {
            int id = tid + it * 256;
            int r  = id >> 4;
            int c4 = (id & 15) * 4;
            *(float4*)&Ws[r][c4] = *(const float4*)&wo[(size_t)(k0 + r) * U + c4];
        }
        __syncthreads();

        #pragma unroll
        for (int k = 0; k < 32; k++) {
            float a[8], bb[4];
            #pragma unroll
            for (int i = 0; i < 8; i++) a[i] = As[k][ty*8 + i];
            #pragma unroll
            for (int j = 0; j < 4; j++) bb[j] = Ws[k][tx*4 + j];
            #pragma unroll
            for (int i = 0; i < 8; i++)
                #pragma unroll
                for (int j = 0; j < 4; j++)
                    acc[i][j] = fmaf(a[i], bb[j], acc[i][j]);
        }
        __syncthreads();
    }

    #pragma unroll
    for (int i = 0; i < 8; i++) {
        int m = m0 + ty*8 + i;
        #pragma unroll
        for (int j = 0; j < 4; j++) {
            int u = tx*4 + j;
            out[(size_t)m * U + u] = acc[i][j] + bo[u];
        }
    }
}

// ---------------------------------------------------------------------------
extern "C" void kernel_launch(void* const* d_in, const int* in_sizes, int n_in,
                              void* d_out, int out_size)
{
    // ---- Rank-based input classification (element/byte-unit invariant) ----
    // Within each size class, appearance order assumed = reference signature
    // order: (v,k,q), (wq,wk,wv), wo, (bq,bk,bv), bo.
    long long uniq[16];
    int nuniq = 0;
    for (int i = 0; i < n_in && i < 16; i++) {
        long long s = in_sizes[i];
        bool found = false;
        for (int j = 0; j < nuniq; j++) if (uniq[j] == s) { found = true; break; }
        if (!found) uniq[nuniq++] = s;
    }
    for (int a = 0; a < nuniq; a++)
        for (int b2 = a + 1; b2 < nuniq; b2++)
            if (uniq[b2] > uniq[a]) { long long t = uniq[a]; uniq[a] = uniq[b2]; uniq[b2] = t; }

    const float* byRank[5][3] = {};
    int cnt[5] = {0, 0, 0, 0, 0};
    for (int i = 0; i < n_in && i < 16; i++) {
        long long s = in_sizes[i];
        int r = 0;
        for (int j = 0; j < nuniq; j++) if (uniq[j] == s) { r = j; break; }
        if (r < 5 && cnt[r] < 3) byRank[r][cnt[r]++] = (const float*)d_in[i];
    }
    const float* v  = byRank[0][0];
    const float* k  = byRank[0][1];
    const float* q  = byRank[0][2];
    const float* wq = byRank[1][0];
    const float* wk = byRank[1][1];
    const float* wv = byRank[1][2];
    const float* wo = byRank[2][0];
    const float* bq = byRank[3][0];
    const float* bk = byRank[3][1];
    const float* bv = byRank[3][2];
    const float* bo = byRank[4][0];

    // ---- Output layout: RETURN-ORDER packing [out @0 | attn @+OUT_ELEMS] ----
    // Evidence (reinterpreted with the symbol-bug fixed): rounds where offset 0
    // held zeros printed rel_err exactly 1.0; rounds where it held 1/1024
    // printed 0.99844 — both = "Output 0 (out) compared at offset 0".
    float* outp = (float*)d_out;
    float* attn = nullptr;
    long long total_f = (long long)out_size;            // if elements
    long long total_b = (long long)out_size / 4;        // if bytes
    if (total_f >= (long long)OUT_ELEMS + ATTN_ELEMS ||
        total_b >= (long long)OUT_ELEMS + ATTN_ELEMS)
        attn = outp + OUT_ELEMS;

    dim3 projGrid(DM/128, BL/128);        // (8, 32)
    proj_kernel<<<projGrid, 256>>>(q, wq, bq, 0);   // -> g_q
    proj_kernel<<<projGrid, 256>>>(k, wk, bk, 1);   // -> g_k
    proj_kernel<<<projGrid, 256>>>(v, wv, bv, 2);   // -> g_v

    if (attn) {
        dim3 logitsGrid(L/128, L/128, B*H);   // (8, 8, 64)
        logits_kernel<<<logitsGrid, 256>>>(attn, 0, (size_t)L*L);
        softmax_kernel<<<B*H*L, 256>>>(attn);
        dim3 ctxGrid(L/128, 1, B*H);          // (8, 1, 64)
        ctx_kernel<<<ctxGrid, 256>>>(attn, 0, (size_t)L*L);
    } else {
        // Fallback: attn not an output — per-head through g_attn1 (in-kernel).
        dim3 lg(L/128, L/128, 1);
        dim3 cg(L/128, 1, 1);
        for (int z = 0; z < B*H; z++) {
            logits_kernel<<<lg, 256>>>(nullptr, z, 0);
            softmax_kernel<<<L, 256>>>(nullptr);
            ctx_kernel<<<cg, 256>>>(nullptr, z, 0);
        }
    }

    outproj_kernel<<<BL/128, 256>>>(wo, bo, outp);  // 32 blocks
}

// round 11
// speedup vs baseline: 1.6276x; 1.6276x over previous
#include <cuda_runtime.h>
#include <mma.h>

using namespace nvcuda;

// Problem constants
#define B    4
#define L    1024
#define H    16
#define U    64
#define DIN  1024
#define DM   1024        // H*U
#define BL   (B*L)       // 4096
#define OUT_ELEMS  (B*L*U)          // 262144
#define ATTN_ELEMS ((long long)B*H*L*L)  // 67108864

// Scratch (device globals; referenced ONLY from device code).
__device__ float g_q[B*H*L*U];          // head-split Q: (B,H,L,U)
__device__ float g_k[B*H*L*U];
__device__ float g_v[B*H*L*U];
__device__ float g_ctx[BL*DM];          // concat layout (B,L,H*U)
__device__ float g_attn1[L*L];          // per-head scratch for fallback path

// ---------------------------------------------------------------------------
// Kernel 1: projection GEMM via tf32 WMMA.
// C[m,n] = sum_k A[m,k]*W[k,n]   (bias added by biasadd_kernel after)
// Output head-split: outHS[((b*H+h)*L+l)*U+u], n = h*U+u.
// Block tile 128x128, BK=32, 256 threads = 8 warps, warp tile 32x64.
// ---------------------------------------------------------------------------
__global__ __launch_bounds__(256) void proj_wmma(
    const float* __restrict__ A, const float* __restrict__ W, int which)
{
    float* outHS = (which == 0) ? g_q : (which == 1) ? g_k : g_v;

    __shared__ float sA[128][36];   // A tile (tf32 values), ld 36
    __shared__ float sW[32][132];   // W tile (tf32 values), ld 132

    const int bm  = blockIdx.y * 128;
    const int bn  = blockIdx.x * 128;
    const int tid = threadIdx.x;
    const int warp = tid >> 5;
    const int wr = (warp >> 1) * 32;   // warp row offset: 0,32,64,96
    const int wc = (warp & 1) * 64;    // warp col offset: 0,64

    wmma::fragment<wmma::accumulator, 16, 16, 8, float> acc[2][4];
    #pragma unroll
    for (int i = 0; i < 2; i++)
        #pragma unroll
        for (int j = 0; j < 4; j++) wmma::fill_fragment(acc[i][j], 0.0f);

    for (int k0 = 0; k0 < DIN; k0 += 32) {
        // A tile 128x32
        #pragma unroll
        for (int it = 0; it < 4; it++) {
            int id = tid + it * 256;       // 0..1023
            int r  = id >> 3;              // 0..127
            int c4 = (id & 7) * 4;         // 0..28
            float4 t = *(const float4*)&A[(size_t)(bm + r) * DIN + k0 + c4];
            sA[r][c4+0] = wmma::__float_to_tf32(t.x);
            sA[r][c4+1] = wmma::__float_to_tf32(t.y);
            sA[r][c4+2] = wmma::__float_to_tf32(t.z);
            sA[r][c4+3] = wmma::__float_to_tf32(t.w);
        }
        // W tile 32x128
        #pragma unroll
        for (int it = 0; it < 4; it++) {
            int id = tid + it * 256;
            int r  = id >> 5;              // 0..31
            int c  = (id & 31) * 4;        // 0..124
            float4 t = *(const float4*)&W[(size_t)(k0 + r) * DM + bn + c];
            sW[r][c+0] = wmma::__float_to_tf32(t.x);
            sW[r][c+1] = wmma::__float_to_tf32(t.y);
            sW[r][c+2] = wmma::__float_to_tf32(t.z);
            sW[r][c+3] = wmma::__float_to_tf32(t.w);
        }
        __syncthreads();

        #pragma unroll
        for (int kk = 0; kk < 4; kk++) {
            wmma::fragment<wmma::matrix_a, 16, 16, 8, wmma::precision::tf32, wmma::row_major> af[2];
            wmma::fragment<wmma::matrix_b, 16, 16, 8, wmma::precision::tf32, wmma::row_major> bf[4];
            #pragma unroll
            for (int i = 0; i < 2; i++)
                wmma::load_matrix_sync(af[i], &sA[wr + i*16][kk*8], 36);
            #pragma unroll
            for (int j = 0; j < 4; j++)
                wmma::load_matrix_sync(bf[j], &sW[kk*8][wc + j*16], 132);
            #pragma unroll
            for (int i = 0; i < 2; i++)
                #pragma unroll
                for (int j = 0; j < 4; j++)
                    wmma::mma_sync(acc[i][j], af[i], bf[j], acc[i][j]);
        }
        __syncthreads();
    }

    // Direct head-split store. Each warp's 64-col span lies within one head.
    const int b_ = bm >> 10;               // 128 | 1024 so constant per block
    #pragma unroll
    for (int i = 0; i < 2; i++) {
        int m  = bm + wr + i*16;
        int l  = m & (L-1);
        #pragma unroll
        for (int j = 0; j < 4; j++) {
            int n  = bn + wc + j*16;
            int h  = n >> 6;
            int u0 = n & 63;
            float* dst = outHS + (((size_t)b_*H + h)*L + l)*U + u0;
            wmma::store_matrix_sync(dst, acc[i][j], U, wmma::mem_row_major);
        }
    }
}

// ---------------------------------------------------------------------------
// Kernel 1b: bias add over a head-split buffer (layout ((b*H+h)*L+l)*U+u).
// bias index n = h*U+u.
// ---------------------------------------------------------------------------
__global__ void biasadd_kernel(const float* __restrict__ bias, int which)
{
    float* buf = (which == 0) ? g_q : (which == 1) ? g_k : g_v;
    size_t idx = (size_t)blockIdx.x * blockDim.x + threadIdx.x;  // over 4M
    int u = idx & 63;
    int h = (idx >> 16) & 15;     // 65536 elems per (b,h)
    buf[idx] += bias[h * U + u];
}

// ---------------------------------------------------------------------------
// Kernel 2: logits via tf32 WMMA. S = Q(LxU) @ K^T(UxL) * 0.125
// Block: 128x128 S tile; BK=32 (2 iters over d=64); warp tile 32x64.
// ---------------------------------------------------------------------------
__global__ __launch_bounds__(256) void logits_wmma(
    float* attnp, int z0, size_t zstride)
{
    float* attn = attnp ? attnp : g_attn1;

    __shared__ float sQ[128][36];
    __shared__ float sK[128][36];

    const int z   = z0 + blockIdx.z;
    const int m0  = blockIdx.y * 128;
    const int n0  = blockIdx.x * 128;
    const int tid = threadIdx.x;
    const int warp = tid >> 5;
    const int wr = (warp >> 1) * 32;
    const int wc = (warp & 1) * 64;

    const float* Q = g_q + (size_t)z * L * U;
    const float* K = g_k + (size_t)z * L * U;

    wmma::fragment<wmma::accumulator, 16, 16, 8, float> acc[2][4];
    #pragma unroll
    for (int i = 0; i < 2; i++)
        #pragma unroll
        for (int j = 0; j < 4; j++) wmma::fill_fragment(acc[i][j], 0.0f);

    for (int k0 = 0; k0 < U; k0 += 32) {
        #pragma unroll
        for (int it = 0; it < 4; it++) {
            int id = tid + it * 256;
            int r  = id >> 3;
            int c4 = (id & 7) * 4;
            float4 t = *(const float4*)&Q[(size_t)(m0 + r) * U + k0 + c4];
            sQ[r][c4+0] = wmma::__float_to_tf32(t.x);
            sQ[r][c4+1] = wmma::__float_to_tf32(t.y);
            sQ[r][c4+2] = wmma::__float_to_tf32(t.z);
            sQ[r][c4+3] = wmma::__float_to_tf32(t.w);
            float4 w = *(const float4*)&K[(size_t)(n0 + r) * U + k0 + c4];
            sK[r][c4+0] = wmma::__float_to_tf32(w.x);
            sK[r][c4+1] = wmma::__float_to_tf32(w.y);
            sK[r][c4+2] = wmma::__float_to_tf32(w.z);
            sK[r][c4+3] = wmma::__float_to_tf32(w.w);
        }
        __syncthreads();

        #pragma unroll
        for (int kk = 0; kk < 4; kk++) {
            wmma::fragment<wmma::matrix_a, 16, 16, 8, wmma::precision::tf32, wmma::row_major> af[2];
            wmma::fragment<wmma::matrix_b, 16, 16, 8, wmma::precision::tf32, wmma::col_major> bf[4];
            #pragma unroll
            for (int i = 0; i < 2; i++)
                wmma::load_matrix_sync(af[i], &sQ[wr + i*16][kk*8], 36);
            #pragma unroll
            for (int j = 0; j < 4; j++)
                wmma::load_matrix_sync(bf[j], &sK[wc + j*16][kk*8], 36);
            #pragma unroll
            for (int i = 0; i < 2; i++)
                #pragma unroll
                for (int j = 0; j < 4; j++)
                    wmma::mma_sync(acc[i][j], af[i], bf[j], acc[i][j]);
        }
        __syncthreads();
    }

    #pragma unroll
    for (int i = 0; i < 2; i++) {
        #pragma unroll
        for (int j = 0; j < 4; j++) {
            #pragma unroll
            for (int t = 0; t < acc[i][j].num_elements; t++)
                acc[i][j].x[t] *= 0.125f;
            float* dst = attn + (size_t)blockIdx.z * zstride
                       + (size_t)(m0 + wr + i*16) * L + (n0 + wc + j*16);
            wmma::store_matrix_sync(dst, acc[i][j], L, wmma::mem_row_major);
        }
    }
}

// ---------------------------------------------------------------------------
// Kernel 3: row softmax in-place. One block (256 thr) per row of 1024.
// ---------------------------------------------------------------------------
__global__ __launch_bounds__(256) void softmax_kernel(float* attnp)
{
    float* attn = attnp ? attnp : g_attn1;
    const int tid = threadIdx.x;
    float4* p = (float4*)(attn + (size_t)blockIdx.x * L);
    float4 v = p[tid];

    float m = fmaxf(fmaxf(v.x, v.y), fmaxf(v.z, v.w));
    #pragma unroll
    for (int o = 16; o > 0; o >>= 1) m = fmaxf(m, __shfl_xor_sync(0xffffffffu, m, o));
    __shared__ float sm[8];
    __shared__ float ss[8];
    int wid = tid >> 5, lane = tid & 31;
    if (lane == 0) sm[wid] = m;
    __syncthreads();
    m = sm[0];
    #pragma unroll
    for (int i = 1; i < 8; i++) m = fmaxf(m, sm[i]);

    v.x = __expf(v.x - m); v.y = __expf(v.y - m);
    v.z = __expf(v.z - m); v.w = __expf(v.w - m);
    float s = v.x + v.y + v.z + v.w;
    #pragma unroll
    for (int o = 16; o > 0; o >>= 1) s += __shfl_xor_sync(0xffffffffu, s, o);
    if (lane == 0) ss[wid] = s;
    __syncthreads();
    s = 0.f;
    #pragma unroll
    for (int i = 0; i < 8; i++) s += ss[i];

    float inv = 1.0f / s;
    v.x *= inv; v.y *= inv; v.z *= inv; v.w *= inv;
    p[tid] = v;
}

// ---------------------------------------------------------------------------
// Kernel 4: ctx via tf32 WMMA. ctx(LxU) = attn(LxL) @ V(LxU)
// Block: 128 rows x 64 cols; BK=32; 8 warps, warp tile 32x32.
// ---------------------------------------------------------------------------
__global__ __launch_bounds__(256) void ctx_wmma(
    const float* attnp, int z0, size_t zstride)
{
    const float* attn = attnp ? attnp : g_attn1;

    __shared__ float sP[128][36];
    __shared__ float sV[32][68];

    const int z   = z0 + blockIdx.z;
    const int m0  = blockIdx.x * 128;
    const int tid = threadIdx.x;
    const int warp = tid >> 5;
    const int wr = (warp >> 1) * 32;   // 0,32,64,96
    const int wc = (warp & 1) * 32;    // 0,32

    const float* Vh = g_v + (size_t)z * L * U;
    const float* attnZ = attn + (size_t)blockIdx.z * zstride;

    wmma::fragment<wmma::accumulator, 16, 16, 8, float> acc[2][2];
    #pragma unroll
    for (int i = 0; i < 2; i++)
        #pragma unroll
        for (int j = 0; j < 2; j++) wmma::fill_fragment(acc[i][j], 0.0f);

    for (int kk0 = 0; kk0 < L; kk0 += 32) {
        // attn tile 128x32
        #pragma unroll
        for (int it = 0; it < 4; it++) {
            int id = tid + it * 256;
            int r  = id >> 3;
            int c4 = (id & 7) * 4;
            float4 t = *(const float4*)&attnZ[(size_t)(m0 + r) * L + kk0 + c4];
            sP[r][c4+0] = wmma::__float_to_tf32(t.x);
            sP[r][c4+1] = wmma::__float_to_tf32(t.y);
            sP[r][c4+2] = wmma::__float_to_tf32(t.z);
            sP[r][c4+3] = wmma::__float_to_tf32(t.w);
        }
        // V tile 32x64
        #pragma unroll
        for (int it = 0; it < 2; it++) {
            int id = tid + it * 256;       // 0..511
            int r  = id >> 4;              // 0..31
            int c4 = (id & 15) * 4;        // 0..60
            float4 t = *(const float4*)&Vh[(size_t)(kk0 + r) * U + c4];
            sV[r][c4+0] = wmma::__float_to_tf32(t.x);
            sV[r][c4+1] = wmma::__float_to_tf32(t.y);
            sV[r][c4+2] = wmma::__float_to_tf32(t.z);
            sV[r][c4+3] = wmma::__float_to_tf32(t.w);
        }
        __syncthreads();

        #pragma unroll
        for (int kk = 0; kk < 4; kk++) {
            wmma::fragment<wmma::matrix_a, 16, 16, 8, wmma::precision::tf32, wmma::row_major> af[2];
            wmma::fragment<wmma::matrix_b, 16, 16, 8, wmma::precision::tf32, wmma::row_major> bf[2];
            #pragma unroll
            for (int i = 0; i < 2; i++)
                wmma::load_matrix_sync(af[i], &sP[wr + i*16][kk*8], 36);
            #pragma unroll
            for (int j = 0; j < 2; j++)
                wmma::load_matrix_sync(bf[j], &sV[kk*8][wc + j*16], 68);
            #pragma unroll
            for (int i = 0; i < 2; i++)
                #pragma unroll
                for (int j = 0; j < 2; j++)
                    wmma::mma_sync(acc[i][j], af[i], bf[j], acc[i][j]);
        }
        __syncthreads();
    }

    // Store into concat layout g_ctx[(b*L + m)*DM + h*U + u]
    const int b_ = z / H, h = z % H;
    #pragma unroll
    for (int i = 0; i < 2; i++) {
        int m = m0 + wr + i*16;
        #pragma unroll
        for (int j = 0; j < 2; j++) {
            float* dst = g_ctx + ((size_t)b_*L + m) * DM + h*U + wc + j*16;
            wmma::store_matrix_sync(dst, acc[i][j], DM, wmma::mem_row_major);
        }
    }
}

// ---------------------------------------------------------------------------
// Kernel 5: output projection (fp32). out(BLxU) = g_ctx(BLxDM) @ wo(DMxU) + bo
// ---------------------------------------------------------------------------
__global__ __launch_bounds__(256) void outproj_kernel(
    const float* __restrict__ wo, const float* __restrict__ bo,
    float* __restrict__ out)
{
    __shared__ float As[32][128];
    __shared__ float Ws[32][64];

    const int m0 = blockIdx.x * 128;
    const int tid = threadIdx.x;
    const int ty = tid >> 4, tx = tid & 15;

    float acc[8][4];
    #pragma unroll
    for (int i = 0; i < 8; i++)
        #pragma unroll
        for (int j = 0; j < 4; j++) acc[i][j] = 0.f;

    for (int k0 = 0; k0 < DM; k0 += 32) {
        #pragma unroll
        for (int it = 0; it < 4; it++) {
            int id = tid + it * 256;
            int r  = id >> 3;
            int c4 = (id & 7) * 4;
            float4 v = *(const float4*)&g_ctx[(size_t)(m0 + r) * DM + k0 + c4];
            As[c4+0][r] = v.x; As[c4+1][r] = v.y;
            As[c4+2][r] = v.z; As[c4+3][r] = v.w;
        }
        #pragma unroll
        for (int it = 0; it < 2; it++) {
            int id = tid + it * 256;
            int r  = id >> 4;
            int c4 = (id & 15) * 4;
            *(float4*)&Ws[r][c4] = *(const float4*)&wo[(size_t)(k0 + r) * U + c4];
        }
        __syncthreads();

        #pragma unroll
        for (int k = 0; k < 32; k++) {
            float a[8], bb[4];
            #pragma unroll
            for (int i = 0; i < 8; i++) a[i] = As[k][ty*8 + i];
            #pragma unroll
            for (int j = 0; j < 4; j++) bb[j] = Ws[k][tx*4 + j];
            #pragma unroll
            for (int i = 0; i < 8; i++)
                #pragma unroll
                for (int j = 0; j < 4; j++)
                    acc[i][j] = fmaf(a[i], bb[j], acc[i][j]);
        }
        __syncthreads();
    }

    #pragma unroll
    for (int i = 0; i < 8; i++) {
        int m = m0 + ty*8 + i;
        #pragma unroll
        for (int j = 0; j < 4; j++) {
            int u = tx*4 + j;
            out[(size_t)m * U + u] = acc[i][j] + bo[u];
        }
    }
}

// ---------------------------------------------------------------------------
extern "C" void kernel_launch(void* const* d_in, const int* in_sizes, int n_in,
                              void* d_out, int out_size)
{
    // Rank-based input classification; within a size class appearance order
    // = reference signature order: (v,k,q), (wq,wk,wv), wo, (bq,bk,bv), bo.
    long long uniq[16];
    int nuniq = 0;
    for (int i = 0; i < n_in && i < 16; i++) {
        long long s = in_sizes[i];
        bool found = false;
        for (int j = 0; j < nuniq; j++) if (uniq[j] == s) { found = true; break; }
        if (!found) uniq[nuniq++] = s;
    }
    for (int a = 0; a < nuniq; a++)
        for (int b2 = a + 1; b2 < nuniq; b2++)
            if (uniq[b2] > uniq[a]) { long long t = uniq[a]; uniq[a] = uniq[b2]; uniq[b2] = t; }

    const float* byRank[5][3] = {};
    int cnt[5] = {0, 0, 0, 0, 0};
    for (int i = 0; i < n_in && i < 16; i++) {
        long long s = in_sizes[i];
        int r = 0;
        for (int j = 0; j < nuniq; j++) if (uniq[j] == s) { r = j; break; }
        if (r < 5 && cnt[r] < 3) byRank[r][cnt[r]++] = (const float*)d_in[i];
    }
    const float* v  = byRank[0][0];
    const float* k  = byRank[0][1];
    const float* q  = byRank[0][2];
    const float* wq = byRank[1][0];
    const float* wk = byRank[1][1];
    const float* wv = byRank[1][2];
    const float* wo = byRank[2][0];
    const float* bq = byRank[3][0];
    const float* bk = byRank[3][1];
    const float* bv = byRank[3][2];
    const float* bo = byRank[4][0];

    // Output layout (verified R10): [out @0 | attn @+OUT_ELEMS]
    float* outp = (float*)d_out;
    float* attn = nullptr;
    long long total_f = (long long)out_size;
    long long total_b = (long long)out_size / 4;
    if (total_f >= (long long)OUT_ELEMS + ATTN_ELEMS ||
        total_b >= (long long)OUT_ELEMS + ATTN_ELEMS)
        attn = outp + OUT_ELEMS;

    dim3 projGrid(DM/128, BL/128);        // (8, 32)
    proj_wmma<<<projGrid, 256>>>(q, wq, 0);   // -> g_q
    proj_wmma<<<projGrid, 256>>>(k, wk, 1);   // -> g_k
    proj_wmma<<<projGrid, 256>>>(v, wv, 2);   // -> g_v
    biasadd_kernel<<<(B*H*L*U)/256, 256>>>(bq, 0);
    biasadd_kernel<<<(B*H*L*U)/256, 256>>>(bk, 1);
    biasadd_kernel<<<(B*H*L*U)/256, 256>>>(bv, 2);

    if (attn) {
        dim3 logitsGrid(L/128, L/128, B*H);   // (8, 8, 64)
        logits_wmma<<<logitsGrid, 256>>>(attn, 0, (size_t)L*L);
        softmax_kernel<<<B*H*L, 256>>>(attn);
        dim3 ctxGrid(L/128, 1, B*H);          // (8, 1, 64)
        ctx_wmma<<<ctxGrid, 256>>>(attn, 0, (size_t)L*L);
    } else {
        dim3 lg(L/128, L/128, 1);
        dim3 cg(L/128, 1, 1);
        for (int z = 0; z < B*H; z++) {
            logits_wmma<<<lg, 256>>>(nullptr, z, 0);
            softmax_kernel<<<L, 256>>>(nullptr);
            ctx_wmma<<<cg, 256>>>(nullptr, z, 0);
        }
    }

    outproj_kernel<<<BL/128, 256>>>(wo, bo, outp);  // 32 blocks
}